// round 15
// baseline (speedup 1.0000x reference)
#include <cuda_runtime.h>
#include <cuda_fp16.h>
#include <cstdint>

// ============================ device scratch ============================
#define MAX_B 8192
__device__ float g_pooled[MAX_B * 128];
__device__ int   g_cumsum[MAX_B];
// f16 weight images Wt[n][k]: [layer][128*136]; 0=i1',1=i2,2=j1',3=j2
__device__ __align__(16) __half g_wimg[4][128 * 136];

// ============================ constants ============================
#define RN       128
#define TILE_M   128
#define THREADS  256

#define KST1     72     // f16 stride, K=64 (144B rows, conflict-free ldsm)
#define KSTEPS1  4
#define KST2     136    // K=128 (272B rows, conflict-free ldsm)
#define KSTEPS2  8

#define HX_BYTES  (TILE_M * KST1 * 2)          // 18432
#define ACT_BYTES (TILE_M * KST2 * 2)          // 34816
#define W1_BYTES  (128 * KST1 * 2)             // 18432
#define W2_BYTES  (128 * KST2 * 2)             // 34816
#define OFF_HX   0
#define OFF_ACT  HX_BYTES                       // 18432
#define OFF_WL1  (OFF_ACT + ACT_BYTES)          // 53248
#define OFF_WL2  (OFF_WL1 + W1_BYTES)           // 71680
#define OFF_BIAS (OFF_WL2 + W2_BYTES)           // 106496 : 4*128 f32
#define OFF_GIDX (OFF_BIAS + 2048)              // 108544 : 128 ints
#define OFF_MASK (OFF_GIDX + 512)               // 109056 : 128 f32
#define SMEM_SZ  (OFF_MASK + 512)               // 109568 (x2 -> 2 CTAs/SM)

// ============================ ptx helpers ============================
__device__ __forceinline__ uint32_t smem_u32(const void* p) {
    uint32_t a;
    asm("{ .reg .u64 t; cvta.to.shared.u64 t, %1; cvt.u32.u64 %0, t; }" : "=r"(a) : "l"(p));
    return a;
}
__device__ __forceinline__ void ldsm4(uint32_t r[4], uint32_t a) {
    asm volatile("ldmatrix.sync.aligned.m8n8.x4.shared.b16 {%0,%1,%2,%3}, [%4];"
                 : "=r"(r[0]), "=r"(r[1]), "=r"(r[2]), "=r"(r[3]) : "r"(a));
}
__device__ __forceinline__ void mma16816(float c[4], const uint32_t a[4], uint32_t b0, uint32_t b1) {
    asm volatile(
        "mma.sync.aligned.m16n8k16.row.col.f32.f16.f16.f32 "
        "{%0,%1,%2,%3}, {%4,%5,%6,%7}, {%8,%9}, {%0,%1,%2,%3};"
        : "+f"(c[0]), "+f"(c[1]), "+f"(c[2]), "+f"(c[3])
        : "r"(a[0]), "r"(a[1]), "r"(a[2]), "r"(a[3]), "r"(b0), "r"(b1));
}
__device__ __forceinline__ void cp16(uint32_t dst, const void* src) {
    asm volatile("cp.async.cg.shared.global [%0], [%1], 16;" :: "r"(dst), "l"(src));
}
#define CP_COMMIT() asm volatile("cp.async.commit_group;" ::: "memory")
#define CP_WAIT0()  asm volatile("cp.async.wait_group 0;" ::: "memory")
#define CP_WAIT1()  asm volatile("cp.async.wait_group 1;" ::: "memory")

// ============================ math helpers ============================
__device__ __forceinline__ float fast_ex2(float x) { float r; asm("ex2.approx.ftz.f32 %0, %1;" : "=f"(r) : "f"(x)); return r; }
__device__ __forceinline__ float fast_tanh(float x) { float r; asm("tanh.approx.f32 %0, %1;" : "=f"(r) : "f"(x)); return r; }
#define L2E 1.4426950408889634f
__device__ __forceinline__ float sigmoid_fast(float x) {
    return fmaf(fast_tanh(0.5f * x), 0.5f, 0.5f);
}
__device__ __forceinline__ float selu_f(float x) {
    float e = fast_ex2(x * L2E);
    float neg = 1.6732632423543772f * (e - 1.0f);
    return 1.0507009873554805f * ((x > 0.0f) ? x : neg);
}
__device__ __forceinline__ uint32_t pkh2(float e0, float e1) {
    uint32_t r; asm("cvt.rn.f16x2.f32 %0, %1, %2;" : "=r"(r) : "f"(e1), "f"(e0)); return r;
}
__device__ __forceinline__ float2 uph2(uint32_t v) {
    __half2 h = *reinterpret_cast<__half2*>(&v);
    return __half22float2(h);
}

// ============================ prologue kernels ============================
__global__ void scan_zero_kernel(const int* __restrict__ nn, int B) {
    int total4 = (B * RN) >> 2;
    float4 z = make_float4(0.0f, 0.0f, 0.0f, 0.0f);
    for (int i = threadIdx.x; i < total4; i += 1024)
        ((float4*)g_pooled)[i] = z;

    __shared__ int s[1024];
    int tid = threadIdx.x;
    int per = (B + 1023) >> 10;
    if (per > 8) per = 8;
    int base = tid * per;
    int loc[8];
    int sum = 0;
    for (int e = 0; e < per; e++) {
        int idx = base + e;
        int v = (idx < B) ? nn[idx] : 0;
        loc[e] = v; sum += v;
    }
    s[tid] = sum;
    __syncthreads();
    for (int off = 1; off < 1024; off <<= 1) {
        int v = (tid >= off) ? s[tid - off] : 0;
        __syncthreads();
        s[tid] += v;
        __syncthreads();
    }
    int run = s[tid] - sum;
    for (int e = 0; e < per; e++) {
        int idx = base + e;
        if (idx < B) { run += loc[e]; g_cumsum[idx] = run; }
    }
}

__global__ void quant_all_kernel(const float* __restrict__ i1w, const float* __restrict__ j1w,
                                 const float* __restrict__ i2w, const float* __restrict__ j2w) {
    int idx = blockIdx.x * blockDim.x + threadIdx.x;
    if (idx < 16384) {
        const float* w = (idx < 8192) ? i1w : j1w;
        int layer = (idx < 8192) ? 0 : 2;
        int e = idx & 8191;
        int n = e >> 6, k = e & 63;
        float v = w[k * 128 + n];
        if (k < 2) v += w[(64 + k) * 128 + n];
        g_wimg[layer][n * KST1 + k] = __float2half(v);
    } else if (idx < 49152) {
        const float* w = (idx < 32768) ? i2w : j2w;
        int layer = (idx < 32768) ? 1 : 3;
        int e = (idx - 16384) & 16383;
        int n = e >> 7, k = e & 127;
        g_wimg[layer][n * KST2 + k] = __float2half(w[k * 128 + n]);
    }
}

// ============================ gemm pieces ============================
__device__ __forceinline__ void prefetch_w(uint32_t sb, uint32_t dstOff, int layer, int bytes) {
    const char* src = (const char*)&g_wimg[layer][0];
    uint32_t dst = sb + dstOff;
    int n16 = bytes >> 4;
    for (int i = threadIdx.x; i < n16; i += THREADS)
        cp16(dst + (uint32_t)(i * 16), src + i * 16);
    CP_COMMIT();
}

__device__ __forceinline__ void zero_acc(float acc[2][8][4]) {
#pragma unroll
    for (int a = 0; a < 2; a++)
#pragma unroll
        for (int b = 0; b < 8; b++)
#pragma unroll
            for (int c = 0; c < 4; c++) acc[a][b][c] = 0.0f;
}

// single-pass: A * W; warp covers 32 rows x 64 cols.
// A fragments issued FIRST so the first MMA's scoreboard deps (a0, b[0]) are the
// earliest-issued loads — shortens the exposed head after each barrier.
template <int KSTEPS, int KST>
__device__ __forceinline__ void gemm_pass(uint32_t aBase, uint32_t wBase,
                                          float acc[2][8][4], int wm, int wn, int lane) {
    uint32_t aAddr = aBase + (uint32_t)(((wm * 32 + (lane & 15)) * KST + 8 * (lane >> 4)) * 2);
    uint32_t bAddr = wBase + (uint32_t)(((wn * 64 + (lane & 7) + 8 * (lane >> 4)) * KST
                                         + 8 * ((lane >> 3) & 1)) * 2);
#pragma unroll
    for (int ks = 0; ks < KSTEPS; ks++) {
        uint32_t a0[4], a1[4];
        ldsm4(a0, aAddr); ldsm4(a1, aAddr + 16 * KST * 2); aAddr += 32;
        uint32_t b[4][4];
#pragma unroll
        for (int g = 0; g < 4; g++) ldsm4(b[g], bAddr + g * (16 * KST * 2));
        bAddr += 32;
#pragma unroll
        for (int g = 0; g < 4; g++) {
            mma16816(acc[0][2 * g],     a0, b[g][0], b[g][1]);
            mma16816(acc[0][2 * g + 1], a0, b[g][2], b[g][3]);
            mma16816(acc[1][2 * g],     a1, b[g][0], b[g][1]);
            mma16816(acc[1][2 * g + 1], a1, b[g][2], b[g][3]);
        }
    }
}

// ACT 1 = tanh (HW approx), 2 = selu: bias + act + single-f16 store
template <int ACT>
__device__ __forceinline__ void epilogue_act(float acc[2][8][4], char* sm, int biasIdx,
                                             int wm, int wn, int lane) {
    const float* bias = (const float*)(sm + OFF_BIAS) + biasIdx * 128;
    char* actB = sm + OFF_ACT;
    int mb = wm * 32 + (lane >> 2);
#pragma unroll
    for (int nt = 0; nt < 8; nt++) {
        int n = wn * 64 + nt * 8 + 2 * (lane & 3);
        float2 bv = *(const float2*)&bias[n];
#pragma unroll
        for (int mt = 0; mt < 2; mt++)
#pragma unroll
            for (int half = 0; half < 2; half++) {
                int m = mb + mt * 16 + half * 8;
                float x0 = acc[mt][nt][2 * half]     + bv.x;
                float x1 = acc[mt][nt][2 * half + 1] + bv.y;
                x0 = (ACT == 1) ? fast_tanh(x0) : selu_f(x0);
                x1 = (ACT == 1) ? fast_tanh(x1) : selu_f(x1);
                *(uint32_t*)(actB + (m * KST2 + n) * 2) = pkh2(x0, x1);
            }
    }
}

// ============================ fused main kernel ============================
__global__ void __launch_bounds__(THREADS, 2)
fused_kernel(const float* __restrict__ nodes, const float* __restrict__ nmask,
             const float* __restrict__ i1b, const float* __restrict__ i2b,
             const float* __restrict__ j1b, const float* __restrict__ j2b,
             int N, int B) {
    extern __shared__ char sm[];
    uint32_t sb = smem_u32(sm);
    int tid = threadIdx.x;
    int lane = tid & 31, wid = tid >> 5;
    int wm = wid & 3, wn = wid >> 2;     // 4 x 2 warp grid: 32 rows x 64 cols each

    float* biasS = (float*)(sm + OFF_BIAS);
    int*   gidxS = (int*)(sm + OFF_GIDX);
    float* maskS = (float*)(sm + OFF_MASK);

    prefetch_w(sb, OFF_WL1, 0, W1_BYTES);   // Wi1' (group A)
    prefetch_w(sb, OFF_WL2, 1, W2_BYTES);   // Wi2  (group B)

    for (int i = tid; i < 512; i += THREADS) {
        const float* bp = (i < 128) ? i1b : (i < 256) ? i2b : (i < 384) ? j1b : j2b;
        biasS[i] = bp[i & 127];
    }
    if (tid < TILE_M) {
        int gn = blockIdx.x * TILE_M + tid;
        maskS[tid] = (gn < N) ? nmask[gn] : 0.0f;
        int lo = 0, hi = B - 1;
        while (lo < hi) {
            int mid = (lo + hi) >> 1;
            if (gn < g_cumsum[mid]) hi = mid; else lo = mid + 1;
        }
        gidxS[tid] = lo;
    }

    // ---- load + quantize x tile [128 x 64] single f16; 2 threads per row ----
    {
        int m = tid & 127, h = tid >> 7;
        int gn = blockIdx.x * TILE_M + m;
        char* xB = sm + OFF_HX;
        float xv[32];
        if (gn < N) {
#pragma unroll
            for (int v4 = 0; v4 < 8; v4++)
                ((float4*)xv)[v4] = *(const float4*)&nodes[(size_t)gn * 64 + h * 32 + v4 * 4];
        } else {
#pragma unroll
            for (int i = 0; i < 32; i++) xv[i] = 0.0f;
        }
        uint32_t hw[16];
#pragma unroll
        for (int p = 0; p < 16; p++) hw[p] = pkh2(xv[2 * p], xv[2 * p + 1]);
        int base = m * (KST1 * 2) + h * 64;
#pragma unroll
        for (int v4 = 0; v4 < 4; v4++)
            *(uint4*)(xB + base + v4 * 16) = ((uint4*)hw)[v4];
    }

    uint32_t hx = sb + OFF_HX;
    uint32_t ac = sb + OFF_ACT;
    uint32_t wl1 = sb + OFF_WL1, wl2 = sb + OFF_WL2;

    CP_WAIT1();          // Wi1' done
    __syncthreads();

    float acc[2][8][4];
    uint32_t rih[2][8][2];   // i2 output (+bias) packed f16x2

    // ===== G1: i layer-1 (WL1 = Wi1') =====
    zero_acc(acc);
    gemm_pass<KSTEPS1, KST1>(hx, wl1, acc, wm, wn, lane);
    epilogue_act<1>(acc, sm, 0, wm, wn, lane);
    CP_WAIT0();          // Wi2 done
    __syncthreads();

    // ===== G2: i layer-2 (WL2 = Wi2) -> packed regs; copy Wj1' underneath =====
    prefetch_w(sb, OFF_WL1, 2, W1_BYTES);
    zero_acc(acc);
    gemm_pass<KSTEPS2, KST2>(ac, wl2, acc, wm, wn, lane);
    {
        const float* bias = biasS + 1 * 128;
#pragma unroll
        for (int nt = 0; nt < 8; nt++) {
            int n = wn * 64 + nt * 8 + 2 * (lane & 3);
            float2 bv = *(const float2*)&bias[n];
#pragma unroll
            for (int mt = 0; mt < 2; mt++) {
                rih[mt][nt][0] = pkh2(acc[mt][nt][0] + bv.x, acc[mt][nt][1] + bv.y);
                rih[mt][nt][1] = pkh2(acc[mt][nt][2] + bv.x, acc[mt][nt][3] + bv.y);
            }
        }
    }
    CP_WAIT0(); __syncthreads();

    // ===== G3: j layer-1 (WL1 = Wj1'); copy Wj2 underneath =====
    prefetch_w(sb, OFF_WL2, 3, W2_BYTES);
    zero_acc(acc);
    gemm_pass<KSTEPS1, KST1>(hx, wl1, acc, wm, wn, lane);
    epilogue_act<2>(acc, sm, 2, wm, wn, lane);
    CP_WAIT0(); __syncthreads();

    // ===== G4: j layer-2 (WL2 = Wj2) =====
    zero_acc(acc);
    gemm_pass<KSTEPS2, KST2>(ac, wl2, acc, wm, wn, lane);

    // ===== gate + pooled reduction (register path) =====
    {
        const float* bias = biasS + 3 * 128;
        int r0 = wm * 32;
        bool uniform = (gidxS[r0] == gidxS[r0 + 31]);
        int baseRow = r0 + (lane >> 2);
        float mk[2][2];
#pragma unroll
        for (int mt = 0; mt < 2; mt++)
#pragma unroll
            for (int half = 0; half < 2; half++)
                mk[mt][half] = maskS[baseRow + mt * 16 + half * 8];

        if (uniform) {
            int g = gidxS[r0];
#pragma unroll
            for (int nt = 0; nt < 8; nt++) {
                int n = wn * 64 + nt * 8 + 2 * (lane & 3);
                float2 bv = *(const float2*)&bias[n];
                // precompute sigmoid factors first (MUFU off the shuffle chain's head)
                float sg[2][2][2];
#pragma unroll
                for (int mt = 0; mt < 2; mt++)
#pragma unroll
                    for (int half = 0; half < 2; half++) {
                        float2 iv = uph2(rih[mt][nt][half]);
                        sg[mt][half][0] = sigmoid_fast(iv.x) * mk[mt][half];
                        sg[mt][half][1] = sigmoid_fast(iv.y) * mk[mt][half];
                    }
                float s0 = 0.0f, s1 = 0.0f;
#pragma unroll
                for (int mt = 0; mt < 2; mt++)
#pragma unroll
                    for (int half = 0; half < 2; half++) {
                        s0 = fmaf(sg[mt][half][0], acc[mt][nt][2 * half] + bv.x, s0);
                        s1 = fmaf(sg[mt][half][1], acc[mt][nt][2 * half + 1] + bv.y, s1);
                    }
#pragma unroll
                for (int st = 4; st <= 16; st <<= 1) {
                    s0 += __shfl_xor_sync(0xffffffffu, s0, st);
                    s1 += __shfl_xor_sync(0xffffffffu, s1, st);
                }
                if ((lane >> 2) == 0) {
                    int nc = wn * 64 + nt * 8 + 2 * lane;
                    atomicAdd(&g_pooled[g * RN + nc], s0);
                    atomicAdd(&g_pooled[g * RN + nc + 1], s1);
                }
            }
        } else {
#pragma unroll
            for (int nt = 0; nt < 8; nt++) {
                int n = wn * 64 + nt * 8 + 2 * (lane & 3);
                float2 bv = *(const float2*)&bias[n];
#pragma unroll
                for (int mt = 0; mt < 2; mt++)
#pragma unroll
                    for (int half = 0; half < 2; half++) {
                        int r = baseRow + mt * 16 + half * 8;
                        int g = gidxS[r];
                        float2 iv = uph2(rih[mt][nt][half]);
                        float v0 = sigmoid_fast(iv.x)
                                   * (acc[mt][nt][2 * half] + bv.x) * mk[mt][half];
                        float v1 = sigmoid_fast(iv.y)
                                   * (acc[mt][nt][2 * half + 1] + bv.y) * mk[mt][half];
                        atomicAdd(&g_pooled[g * RN + n], v0);
                        atomicAdd(&g_pooled[g * RN + n + 1], v1);
                    }
            }
        }
    }
}

// ============================ final per-graph MLP (split-K, 2 warps/graph) ============================
#define FG 4   // graphs per block
__global__ void final_kernel(const float* __restrict__ h1w, const float* __restrict__ h1b,
                             const float* __restrict__ h2w, const float* __restrict__ h2b,
                             float* __restrict__ out, int B) {
    __shared__ float ps[FG * RN];          // pooled rows
    __shared__ float pstage[FG][132];      // upper-warp partials
    int g0 = blockIdx.x * FG;
    int tid = threadIdx.x;
    if (tid < 128) {
        int idx = tid * 4;
        int g = g0 + (idx >> 7);
        float4 v = (g < B) ? *(const float4*)&g_pooled[(size_t)g * RN + (idx & 127)]
                           : make_float4(0.f, 0.f, 0.f, 0.f);
        *(float4*)&ps[idx] = v;
    }
    __syncthreads();

    int w = tid >> 5, lane = tid & 31;
    int gi = w >> 1, kh = w & 1;           // graph index within block, k-half
    float a0, a1, a2, a3;
    if (kh == 0) {
        float4 bv = ((const float4*)h1b)[lane];
        a0 = bv.x; a1 = bv.y; a2 = bv.z; a3 = bv.w;
    } else {
        a0 = a1 = a2 = a3 = 0.0f;
    }
    const float* pr = &ps[gi * RN] + kh * 64;
    const float* wb = h1w + (size_t)kh * 64 * RN;
#pragma unroll 8
    for (int k = 0; k < 64; k++) {
        float pv = pr[k];
        float4 wv = *(const float4*)(wb + k * RN + (lane << 2));
        a0 = fmaf(pv, wv.x, a0);
        a1 = fmaf(pv, wv.y, a1);
        a2 = fmaf(pv, wv.z, a2);
        a3 = fmaf(pv, wv.w, a3);
    }
    if (kh == 1) {
        pstage[gi][lane * 4 + 0] = a0;
        pstage[gi][lane * 4 + 1] = a1;
        pstage[gi][lane * 4 + 2] = a2;
        pstage[gi][lane * 4 + 3] = a3;
    }
    __syncthreads();
    if (kh == 0) {
        int g = g0 + gi;
        if (g >= B) return;
        a0 += pstage[gi][lane * 4 + 0];
        a1 += pstage[gi][lane * 4 + 1];
        a2 += pstage[gi][lane * 4 + 2];
        a3 += pstage[gi][lane * 4 + 3];
        a0 = selu_f(a0); a1 = selu_f(a1); a2 = selu_f(a2); a3 = selu_f(a3);
        float4 h2 = ((const float4*)h2w)[lane];
        float part = a0 * h2.x + a1 * h2.y + a2 * h2.z + a3 * h2.w;
#pragma unroll
        for (int off = 16; off > 0; off >>= 1)
            part += __shfl_down_sync(0xffffffffu, part, off);
        if (lane == 0) out[g] = part + h2b[0];
    }
}

// ============================ launch ============================
extern "C" void kernel_launch(void* const* d_in, const int* in_sizes, int n_in,
                              void* d_out, int out_size) {
    const float* nodes = (const float*)d_in[0];
    const float* nmask = (const float*)d_in[1];
    const int*   n_node = (const int*)d_in[2];
    const float* i1w = (const float*)d_in[3];
    const float* i1b = (const float*)d_in[4];
    const float* i2w = (const float*)d_in[5];
    const float* i2b = (const float*)d_in[6];
    const float* j1w = (const float*)d_in[7];
    const float* j1b = (const float*)d_in[8];
    const float* j2w = (const float*)d_in[9];
    const float* j2b = (const float*)d_in[10];
    const float* h1w = (const float*)d_in[11];
    const float* h1b = (const float*)d_in[12];
    const float* h2w = (const float*)d_in[13];
    const float* h2b = (const float*)d_in[14];

    int N = in_sizes[1];
    int B = in_sizes[2];

    scan_zero_kernel<<<1, 1024>>>(n_node, B);
    quant_all_kernel<<<192, 256>>>(i1w, j1w, i2w, j2w);

    cudaFuncSetAttribute(fused_kernel, cudaFuncAttributeMaxDynamicSharedMemorySize, SMEM_SZ);
    int grid = (N + TILE_M - 1) / TILE_M;
    fused_kernel<<<grid, THREADS, SMEM_SZ>>>(nodes, nmask, i1b, i2b, j1b, j2b, N, B);

    final_kernel<<<(B + FG - 1) / FG, 256>>>(h1w, h1b, h2w, h2b, (float*)d_out, B);
}

// round 16
// speedup vs baseline: 1.0520x; 1.0520x over previous
#include <cuda_runtime.h>
#include <cuda_fp16.h>
#include <cstdint>

// ============================ device scratch ============================
#define MAX_B 8192
__device__ float g_pooled[MAX_B * 128];
__device__ int   g_cumsum[MAX_B];
// f16 weight images Wt[n][k]: [layer][128*136]; 0=i1',1=i2,2=j1',3=j2
__device__ __align__(16) __half g_wimg[4][128 * 136];

// ============================ constants ============================
#define RN       128
#define TILE_M   128
#define THREADS  256

#define KST1     72     // f16 stride, K=64 (144B rows, conflict-free ldsm)
#define KSTEPS1  4
#define KST2     136    // K=128 (272B rows, conflict-free ldsm)
#define KSTEPS2  8

#define HX_BYTES  (TILE_M * KST1 * 2)          // 18432
#define ACT_BYTES (TILE_M * KST2 * 2)          // 34816
#define W1_BYTES  (128 * KST1 * 2)             // 18432
#define W2_BYTES  (128 * KST2 * 2)             // 34816
#define OFF_HX   0
#define OFF_ACT  HX_BYTES                       // 18432
#define OFF_WL1  (OFF_ACT + ACT_BYTES)          // 53248
#define OFF_WL2  (OFF_WL1 + W1_BYTES)           // 71680
#define OFF_BIAS (OFF_WL2 + W2_BYTES)           // 106496 : 4*128 f32
#define OFF_GIDX (OFF_BIAS + 2048)              // 108544 : 128 ints
#define OFF_MASK (OFF_GIDX + 512)               // 109056 : 128 f32
#define SMEM_SZ  (OFF_MASK + 512)               // 109568 (x2 -> 2 CTAs/SM)

// ============================ ptx helpers ============================
__device__ __forceinline__ uint32_t smem_u32(const void* p) {
    uint32_t a;
    asm("{ .reg .u64 t; cvta.to.shared.u64 t, %1; cvt.u32.u64 %0, t; }" : "=r"(a) : "l"(p));
    return a;
}
__device__ __forceinline__ void ldsm4(uint32_t r[4], uint32_t a) {
    asm volatile("ldmatrix.sync.aligned.m8n8.x4.shared.b16 {%0,%1,%2,%3}, [%4];"
                 : "=r"(r[0]), "=r"(r[1]), "=r"(r[2]), "=r"(r[3]) : "r"(a));
}
__device__ __forceinline__ void mma16816(float c[4], const uint32_t a[4], uint32_t b0, uint32_t b1) {
    asm volatile(
        "mma.sync.aligned.m16n8k16.row.col.f32.f16.f16.f32 "
        "{%0,%1,%2,%3}, {%4,%5,%6,%7}, {%8,%9}, {%0,%1,%2,%3};"
        : "+f"(c[0]), "+f"(c[1]), "+f"(c[2]), "+f"(c[3])
        : "r"(a[0]), "r"(a[1]), "r"(a[2]), "r"(a[3]), "r"(b0), "r"(b1));
}
__device__ __forceinline__ void cp16(uint32_t dst, const void* src) {
    asm volatile("cp.async.cg.shared.global [%0], [%1], 16;" :: "r"(dst), "l"(src));
}
#define CP_COMMIT() asm volatile("cp.async.commit_group;" ::: "memory")
#define CP_WAIT0()  asm volatile("cp.async.wait_group 0;" ::: "memory")
#define CP_WAIT1()  asm volatile("cp.async.wait_group 1;" ::: "memory")

// ============================ math helpers ============================
__device__ __forceinline__ float fast_ex2(float x) { float r; asm("ex2.approx.ftz.f32 %0, %1;" : "=f"(r) : "f"(x)); return r; }
__device__ __forceinline__ float fast_tanh(float x) { float r; asm("tanh.approx.f32 %0, %1;" : "=f"(r) : "f"(x)); return r; }
#define L2E 1.4426950408889634f
__device__ __forceinline__ float sigmoid_fast(float x) {
    return fmaf(fast_tanh(0.5f * x), 0.5f, 0.5f);
}
__device__ __forceinline__ float selu_f(float x) {
    float e = fast_ex2(x * L2E);
    float neg = 1.6732632423543772f * (e - 1.0f);
    return 1.0507009873554805f * ((x > 0.0f) ? x : neg);
}
__device__ __forceinline__ uint32_t pkh2(float e0, float e1) {
    uint32_t r; asm("cvt.rn.f16x2.f32 %0, %1, %2;" : "=r"(r) : "f"(e1), "f"(e0)); return r;
}
__device__ __forceinline__ float2 uph2(uint32_t v) {
    __half2 h = *reinterpret_cast<__half2*>(&v);
    return __half22float2(h);
}

// ============================ prologue kernels ============================
// scan only (zeroing moved to quant_all for parallelism)
__global__ void scan_kernel(const int* __restrict__ nn, int B) {
    __shared__ int s[1024];
    int tid = threadIdx.x;
    int per = (B + 1023) >> 10;
    if (per > 8) per = 8;
    int base = tid * per;
    int loc[8];
    int sum = 0;
    for (int e = 0; e < per; e++) {
        int idx = base + e;
        int v = (idx < B) ? nn[idx] : 0;
        loc[e] = v; sum += v;
    }
    s[tid] = sum;
    __syncthreads();
    for (int off = 1; off < 1024; off <<= 1) {
        int v = (tid >= off) ? s[tid - off] : 0;
        __syncthreads();
        s[tid] += v;
        __syncthreads();
    }
    int run = s[tid] - sum;
    for (int e = 0; e < per; e++) {
        int idx = base + e;
        if (idx < B) { run += loc[e]; g_cumsum[idx] = run; }
    }
}

// weight images + parallel pooled zero (192 blocks)
__global__ void quant_all_kernel(const float* __restrict__ i1w, const float* __restrict__ j1w,
                                 const float* __restrict__ i2w, const float* __restrict__ j2w,
                                 int B) {
    int idx = blockIdx.x * blockDim.x + threadIdx.x;
    if (idx < 16384) {
        const float* w = (idx < 8192) ? i1w : j1w;
        int layer = (idx < 8192) ? 0 : 2;
        int e = idx & 8191;
        int n = e >> 6, k = e & 63;
        float v = w[k * 128 + n];
        if (k < 2) v += w[(64 + k) * 128 + n];
        g_wimg[layer][n * KST1 + k] = __float2half(v);
    } else if (idx < 49152) {
        const float* w = (idx < 32768) ? i2w : j2w;
        int layer = (idx < 32768) ? 1 : 3;
        int e = (idx - 16384) & 16383;
        int n = e >> 7, k = e & 127;
        g_wimg[layer][n * KST2 + k] = __float2half(w[k * 128 + n]);
    }
    // parallel zero of g_pooled
    int total4 = (B * RN) >> 2;
    int nthreads = gridDim.x * blockDim.x;
    float4 z = make_float4(0.0f, 0.0f, 0.0f, 0.0f);
    for (int i = idx; i < total4; i += nthreads)
        ((float4*)g_pooled)[i] = z;
}

// ============================ gemm pieces ============================
__device__ __forceinline__ void prefetch_w(uint32_t sb, uint32_t dstOff, int layer, int bytes) {
    const char* src = (const char*)&g_wimg[layer][0];
    uint32_t dst = sb + dstOff;
    int n16 = bytes >> 4;
    for (int i = threadIdx.x; i < n16; i += THREADS)
        cp16(dst + (uint32_t)(i * 16), src + i * 16);
    CP_COMMIT();
}

__device__ __forceinline__ void zero_acc(float acc[2][8][4]) {
#pragma unroll
    for (int a = 0; a < 2; a++)
#pragma unroll
        for (int b = 0; b < 8; b++)
#pragma unroll
            for (int c = 0; c < 4; c++) acc[a][b][c] = 0.0f;
}

// single-pass: A * W; warp covers 32 rows x 64 cols (A fragments issued first)
template <int KSTEPS, int KST>
__device__ __forceinline__ void gemm_pass(uint32_t aBase, uint32_t wBase,
                                          float acc[2][8][4], int wm, int wn, int lane) {
    uint32_t aAddr = aBase + (uint32_t)(((wm * 32 + (lane & 15)) * KST + 8 * (lane >> 4)) * 2);
    uint32_t bAddr = wBase + (uint32_t)(((wn * 64 + (lane & 7) + 8 * (lane >> 4)) * KST
                                         + 8 * ((lane >> 3) & 1)) * 2);
#pragma unroll
    for (int ks = 0; ks < KSTEPS; ks++) {
        uint32_t a0[4], a1[4];
        ldsm4(a0, aAddr); ldsm4(a1, aAddr + 16 * KST * 2); aAddr += 32;
        uint32_t b[4][4];
#pragma unroll
        for (int g = 0; g < 4; g++) ldsm4(b[g], bAddr + g * (16 * KST * 2));
        bAddr += 32;
#pragma unroll
        for (int g = 0; g < 4; g++) {
            mma16816(acc[0][2 * g],     a0, b[g][0], b[g][1]);
            mma16816(acc[0][2 * g + 1], a0, b[g][2], b[g][3]);
            mma16816(acc[1][2 * g],     a1, b[g][0], b[g][1]);
            mma16816(acc[1][2 * g + 1], a1, b[g][2], b[g][3]);
        }
    }
}

// ACT 1 = tanh (HW approx), 2 = selu: bias + act + single-f16 store
template <int ACT>
__device__ __forceinline__ void epilogue_act(float acc[2][8][4], char* sm, int biasIdx,
                                             int wm, int wn, int lane) {
    const float* bias = (const float*)(sm + OFF_BIAS) + biasIdx * 128;
    char* actB = sm + OFF_ACT;
    int mb = wm * 32 + (lane >> 2);
#pragma unroll
    for (int nt = 0; nt < 8; nt++) {
        int n = wn * 64 + nt * 8 + 2 * (lane & 3);
        float2 bv = *(const float2*)&bias[n];
#pragma unroll
        for (int mt = 0; mt < 2; mt++)
#pragma unroll
            for (int half = 0; half < 2; half++) {
                int m = mb + mt * 16 + half * 8;
                float x0 = acc[mt][nt][2 * half]     + bv.x;
                float x1 = acc[mt][nt][2 * half + 1] + bv.y;
                x0 = (ACT == 1) ? fast_tanh(x0) : selu_f(x0);
                x1 = (ACT == 1) ? fast_tanh(x1) : selu_f(x1);
                *(uint32_t*)(actB + (m * KST2 + n) * 2) = pkh2(x0, x1);
            }
    }
}

// ============================ fused main kernel (unchanged from best) ============================
__global__ void __launch_bounds__(THREADS, 2)
fused_kernel(const float* __restrict__ nodes, const float* __restrict__ nmask,
             const float* __restrict__ i1b, const float* __restrict__ i2b,
             const float* __restrict__ j1b, const float* __restrict__ j2b,
             int N, int B) {
    extern __shared__ char sm[];
    uint32_t sb = smem_u32(sm);
    int tid = threadIdx.x;
    int lane = tid & 31, wid = tid >> 5;
    int wm = wid & 3, wn = wid >> 2;     // 4 x 2 warp grid: 32 rows x 64 cols each

    float* biasS = (float*)(sm + OFF_BIAS);
    int*   gidxS = (int*)(sm + OFF_GIDX);
    float* maskS = (float*)(sm + OFF_MASK);

    prefetch_w(sb, OFF_WL1, 0, W1_BYTES);   // Wi1' (group A)
    prefetch_w(sb, OFF_WL2, 1, W2_BYTES);   // Wi2  (group B)

    for (int i = tid; i < 512; i += THREADS) {
        const float* bp = (i < 128) ? i1b : (i < 256) ? i2b : (i < 384) ? j1b : j2b;
        biasS[i] = bp[i & 127];
    }
    if (tid < TILE_M) {
        int gn = blockIdx.x * TILE_M + tid;
        maskS[tid] = (gn < N) ? nmask[gn] : 0.0f;
        int lo = 0, hi = B - 1;
        while (lo < hi) {
            int mid = (lo + hi) >> 1;
            if (gn < g_cumsum[mid]) hi = mid; else lo = mid + 1;
        }
        gidxS[tid] = lo;
    }

    // ---- load + quantize x tile [128 x 64] single f16; 2 threads per row ----
    {
        int m = tid & 127, h = tid >> 7;
        int gn = blockIdx.x * TILE_M + m;
        char* xB = sm + OFF_HX;
        float xv[32];
        if (gn < N) {
#pragma unroll
            for (int v4 = 0; v4 < 8; v4++)
                ((float4*)xv)[v4] = *(const float4*)&nodes[(size_t)gn * 64 + h * 32 + v4 * 4];
        } else {
#pragma unroll
            for (int i = 0; i < 32; i++) xv[i] = 0.0f;
        }
        uint32_t hw[16];
#pragma unroll
        for (int p = 0; p < 16; p++) hw[p] = pkh2(xv[2 * p], xv[2 * p + 1]);
        int base = m * (KST1 * 2) + h * 64;
#pragma unroll
        for (int v4 = 0; v4 < 4; v4++)
            *(uint4*)(xB + base + v4 * 16) = ((uint4*)hw)[v4];
    }

    uint32_t hx = sb + OFF_HX;
    uint32_t ac = sb + OFF_ACT;
    uint32_t wl1 = sb + OFF_WL1, wl2 = sb + OFF_WL2;

    CP_WAIT1();          // Wi1' done
    __syncthreads();

    float acc[2][8][4];
    uint32_t rih[2][8][2];   // i2 output (+bias) packed f16x2

    // ===== G1: i layer-1 (WL1 = Wi1') =====
    zero_acc(acc);
    gemm_pass<KSTEPS1, KST1>(hx, wl1, acc, wm, wn, lane);
    epilogue_act<1>(acc, sm, 0, wm, wn, lane);
    CP_WAIT0();          // Wi2 done
    __syncthreads();

    // ===== G2: i layer-2 (WL2 = Wi2) -> packed regs; copy Wj1' underneath =====
    prefetch_w(sb, OFF_WL1, 2, W1_BYTES);
    zero_acc(acc);
    gemm_pass<KSTEPS2, KST2>(ac, wl2, acc, wm, wn, lane);
    {
        const float* bias = biasS + 1 * 128;
#pragma unroll
        for (int nt = 0; nt < 8; nt++) {
            int n = wn * 64 + nt * 8 + 2 * (lane & 3);
            float2 bv = *(const float2*)&bias[n];
#pragma unroll
            for (int mt = 0; mt < 2; mt++) {
                rih[mt][nt][0] = pkh2(acc[mt][nt][0] + bv.x, acc[mt][nt][1] + bv.y);
                rih[mt][nt][1] = pkh2(acc[mt][nt][2] + bv.x, acc[mt][nt][3] + bv.y);
            }
        }
    }
    CP_WAIT0(); __syncthreads();

    // ===== G3: j layer-1 (WL1 = Wj1'); copy Wj2 underneath =====
    prefetch_w(sb, OFF_WL2, 3, W2_BYTES);
    zero_acc(acc);
    gemm_pass<KSTEPS1, KST1>(hx, wl1, acc, wm, wn, lane);
    epilogue_act<2>(acc, sm, 2, wm, wn, lane);
    CP_WAIT0(); __syncthreads();

    // ===== G4: j layer-2 (WL2 = Wj2) =====
    zero_acc(acc);
    gemm_pass<KSTEPS2, KST2>(ac, wl2, acc, wm, wn, lane);

    // ===== gate + pooled reduction (register path) =====
    {
        const float* bias = biasS + 3 * 128;
        int r0 = wm * 32;
        bool uniform = (gidxS[r0] == gidxS[r0 + 31]);
        int baseRow = r0 + (lane >> 2);
        float mk[2][2];
#pragma unroll
        for (int mt = 0; mt < 2; mt++)
#pragma unroll
            for (int half = 0; half < 2; half++)
                mk[mt][half] = maskS[baseRow + mt * 16 + half * 8];

        if (uniform) {
            int g = gidxS[r0];
#pragma unroll
            for (int nt = 0; nt < 8; nt++) {
                int n = wn * 64 + nt * 8 + 2 * (lane & 3);
                float2 bv = *(const float2*)&bias[n];
                float sg[2][2][2];
#pragma unroll
                for (int mt = 0; mt < 2; mt++)
#pragma unroll
                    for (int half = 0; half < 2; half++) {
                        float2 iv = uph2(rih[mt][nt][half]);
                        sg[mt][half][0] = sigmoid_fast(iv.x) * mk[mt][half];
                        sg[mt][half][1] = sigmoid_fast(iv.y) * mk[mt][half];
                    }
                float s0 = 0.0f, s1 = 0.0f;
#pragma unroll
                for (int mt = 0; mt < 2; mt++)
#pragma unroll
                    for (int half = 0; half < 2; half++) {
                        s0 = fmaf(sg[mt][half][0], acc[mt][nt][2 * half] + bv.x, s0);
                        s1 = fmaf(sg[mt][half][1], acc[mt][nt][2 * half + 1] + bv.y, s1);
                    }
#pragma unroll
                for (int st = 4; st <= 16; st <<= 1) {
                    s0 += __shfl_xor_sync(0xffffffffu, s0, st);
                    s1 += __shfl_xor_sync(0xffffffffu, s1, st);
                }
                if ((lane >> 2) == 0) {
                    int nc = wn * 64 + nt * 8 + 2 * lane;
                    atomicAdd(&g_pooled[g * RN + nc], s0);
                    atomicAdd(&g_pooled[g * RN + nc + 1], s1);
                }
            }
        } else {
#pragma unroll
            for (int nt = 0; nt < 8; nt++) {
                int n = wn * 64 + nt * 8 + 2 * (lane & 3);
                float2 bv = *(const float2*)&bias[n];
#pragma unroll
                for (int mt = 0; mt < 2; mt++)
#pragma unroll
                    for (int half = 0; half < 2; half++) {
                        int r = baseRow + mt * 16 + half * 8;
                        int g = gidxS[r];
                        float2 iv = uph2(rih[mt][nt][half]);
                        float v0 = sigmoid_fast(iv.x)
                                   * (acc[mt][nt][2 * half] + bv.x) * mk[mt][half];
                        float v1 = sigmoid_fast(iv.y)
                                   * (acc[mt][nt][2 * half + 1] + bv.y) * mk[mt][half];
                        atomicAdd(&g_pooled[g * RN + n], v0);
                        atomicAdd(&g_pooled[g * RN + n + 1], v1);
                    }
            }
        }
    }
}

// ============================ final per-graph MLP (split-K4, 4 warps/graph) ============================
#define FG 2   // graphs per block
__global__ void final_kernel(const float* __restrict__ h1w, const float* __restrict__ h1b,
                             const float* __restrict__ h2w, const float* __restrict__ h2b,
                             float* __restrict__ out, int B) {
    __shared__ float ps[FG * RN];            // pooled rows
    __shared__ float pstage[FG][3][132];     // partials from k-quarters 1..3
    int g0 = blockIdx.x * FG;
    int tid = threadIdx.x;
    if (tid < 64) {
        int idx = tid * 4;
        int g = g0 + (idx >> 7);
        float4 v = (g < B) ? *(const float4*)&g_pooled[(size_t)g * RN + (idx & 127)]
                           : make_float4(0.f, 0.f, 0.f, 0.f);
        *(float4*)&ps[idx] = v;
    }
    __syncthreads();

    int w = tid >> 5, lane = tid & 31;
    int gi = w >> 2, kq = w & 3;             // graph in block, k-quarter
    float a0, a1, a2, a3;
    if (kq == 0) {
        float4 bv = ((const float4*)h1b)[lane];
        a0 = bv.x; a1 = bv.y; a2 = bv.z; a3 = bv.w;
    } else {
        a0 = a1 = a2 = a3 = 0.0f;
    }
    const float* pr = &ps[gi * RN] + kq * 32;
    const float* wb = h1w + (size_t)kq * 32 * RN;
#pragma unroll 8
    for (int k = 0; k < 32; k++) {
        float pv = pr[k];
        float4 wv = *(const float4*)(wb + k * RN + (lane << 2));
        a0 = fmaf(pv, wv.x, a0);
        a1 = fmaf(pv, wv.y, a1);
        a2 = fmaf(pv, wv.z, a2);
        a3 = fmaf(pv, wv.w, a3);
    }
    if (kq != 0) {
        pstage[gi][kq - 1][lane * 4 + 0] = a0;
        pstage[gi][kq - 1][lane * 4 + 1] = a1;
        pstage[gi][kq - 1][lane * 4 + 2] = a2;
        pstage[gi][kq - 1][lane * 4 + 3] = a3;
    }
    __syncthreads();
    if (kq == 0) {
        int g = g0 + gi;
        if (g >= B) return;
#pragma unroll
        for (int q = 0; q < 3; q++) {
            a0 += pstage[gi][q][lane * 4 + 0];
            a1 += pstage[gi][q][lane * 4 + 1];
            a2 += pstage[gi][q][lane * 4 + 2];
            a3 += pstage[gi][q][lane * 4 + 3];
        }
        a0 = selu_f(a0); a1 = selu_f(a1); a2 = selu_f(a2); a3 = selu_f(a3);
        float4 h2 = ((const float4*)h2w)[lane];
        float part = a0 * h2.x + a1 * h2.y + a2 * h2.z + a3 * h2.w;
#pragma unroll
        for (int off = 16; off > 0; off >>= 1)
            part += __shfl_down_sync(0xffffffffu, part, off);
        if (lane == 0) out[g] = part + h2b[0];
    }
}

// ============================ launch ============================
extern "C" void kernel_launch(void* const* d_in, const int* in_sizes, int n_in,
                              void* d_out, int out_size) {
    const float* nodes = (const float*)d_in[0];
    const float* nmask = (const float*)d_in[1];
    const int*   n_node = (const int*)d_in[2];
    const float* i1w = (const float*)d_in[3];
    const float* i1b = (const float*)d_in[4];
    const float* i2w = (const float*)d_in[5];
    const float* i2b = (const float*)d_in[6];
    const float* j1w = (const float*)d_in[7];
    const float* j1b = (const float*)d_in[8];
    const float* j2w = (const float*)d_in[9];
    const float* j2b = (const float*)d_in[10];
    const float* h1w = (const float*)d_in[11];
    const float* h1b = (const float*)d_in[12];
    const float* h2w = (const float*)d_in[13];
    const float* h2b = (const float*)d_in[14];

    int N = in_sizes[1];
    int B = in_sizes[2];

    scan_kernel<<<1, 1024>>>(n_node, B);
    quant_all_kernel<<<192, 256>>>(i1w, j1w, i2w, j2w, B);

    cudaFuncSetAttribute(fused_kernel, cudaFuncAttributeMaxDynamicSharedMemorySize, SMEM_SZ);
    int grid = (N + TILE_M - 1) / TILE_M;
    fused_kernel<<<grid, THREADS, SMEM_SZ>>>(nodes, nmask, i1b, i2b, j1b, j2b, N, B);

    final_kernel<<<(B + FG - 1) / FG, 256>>>(h1w, h1b, h2w, h2b, (float*)d_out, B);
}

// round 17
// speedup vs baseline: 1.0538x; 1.0018x over previous
#include <cuda_runtime.h>
#include <cuda_fp16.h>
#include <cstdint>

// ============================ device scratch ============================
#define MAX_B 8192
__device__ float g_pooled[MAX_B * 128];
__device__ int   g_cumsum[MAX_B];
// f16 weight images Wt[n][k]: [layer][128*136]; 0=i1',1=i2,2=j1',3=j2
__device__ __align__(16) __half g_wimg[4][128 * 136];

// ============================ constants ============================
#define RN       128
#define TILE_M   128
#define THREADS  256

#define KST1     72     // f16 stride, K=64 (144B rows, conflict-free ldsm)
#define KSTEPS1  4
#define KST2     136    // K=128 (272B rows, conflict-free ldsm)
#define KSTEPS2  8

#define HX_BYTES  (TILE_M * KST1 * 2)          // 18432
#define ACT_BYTES (TILE_M * KST2 * 2)          // 34816
#define W1_BYTES  (128 * KST1 * 2)             // 18432
#define W2_BYTES  (128 * KST2 * 2)             // 34816
#define OFF_HX   0
#define OFF_ACT  HX_BYTES                       // 18432
#define OFF_WL1  (OFF_ACT + ACT_BYTES)          // 53248
#define OFF_WL2  (OFF_WL1 + W1_BYTES)           // 71680
#define OFF_BIAS (OFF_WL2 + W2_BYTES)           // 106496 : 4*128 f32
#define OFF_GIDX (OFF_BIAS + 2048)              // 108544 : 128 ints
#define OFF_MASK (OFF_GIDX + 512)               // 109056 : 128 f32
#define SMEM_SZ  (OFF_MASK + 512)               // 109568 (x2 -> 2 CTAs/SM)

// ============================ ptx helpers ============================
__device__ __forceinline__ uint32_t smem_u32(const void* p) {
    uint32_t a;
    asm("{ .reg .u64 t; cvta.to.shared.u64 t, %1; cvt.u32.u64 %0, t; }" : "=r"(a) : "l"(p));
    return a;
}
__device__ __forceinline__ void ldsm4(uint32_t r[4], uint32_t a) {
    asm volatile("ldmatrix.sync.aligned.m8n8.x4.shared.b16 {%0,%1,%2,%3}, [%4];"
                 : "=r"(r[0]), "=r"(r[1]), "=r"(r[2]), "=r"(r[3]) : "r"(a));
}
__device__ __forceinline__ void mma16816(float c[4], const uint32_t a[4], uint32_t b0, uint32_t b1) {
    asm volatile(
        "mma.sync.aligned.m16n8k16.row.col.f32.f16.f16.f32 "
        "{%0,%1,%2,%3}, {%4,%5,%6,%7}, {%8,%9}, {%0,%1,%2,%3};"
        : "+f"(c[0]), "+f"(c[1]), "+f"(c[2]), "+f"(c[3])
        : "r"(a[0]), "r"(a[1]), "r"(a[2]), "r"(a[3]), "r"(b0), "r"(b1));
}
__device__ __forceinline__ void cp16(uint32_t dst, const void* src) {
    asm volatile("cp.async.cg.shared.global [%0], [%1], 16;" :: "r"(dst), "l"(src));
}
#define CP_COMMIT() asm volatile("cp.async.commit_group;" ::: "memory")
#define CP_WAIT0()  asm volatile("cp.async.wait_group 0;" ::: "memory")
#define CP_WAIT1()  asm volatile("cp.async.wait_group 1;" ::: "memory")

// ============================ math helpers ============================
__device__ __forceinline__ float fast_ex2(float x) { float r; asm("ex2.approx.ftz.f32 %0, %1;" : "=f"(r) : "f"(x)); return r; }
__device__ __forceinline__ float fast_tanh(float x) { float r; asm("tanh.approx.f32 %0, %1;" : "=f"(r) : "f"(x)); return r; }
#define L2E 1.4426950408889634f
__device__ __forceinline__ float sigmoid_fast(float x) {
    return fmaf(fast_tanh(0.5f * x), 0.5f, 0.5f);
}
__device__ __forceinline__ float selu_f(float x) {
    float e = fast_ex2(x * L2E);
    float neg = 1.6732632423543772f * (e - 1.0f);
    return 1.0507009873554805f * ((x > 0.0f) ? x : neg);
}
__device__ __forceinline__ uint32_t pkh2(float e0, float e1) {
    uint32_t r; asm("cvt.rn.f16x2.f32 %0, %1, %2;" : "=r"(r) : "f"(e1), "f"(e0)); return r;
}
__device__ __forceinline__ float2 uph2(uint32_t v) {
    __half2 h = *reinterpret_cast<__half2*>(&v);
    return __half22float2(h);
}

// ============================ prologue: quant + zero + scan in ONE kernel ============================
__global__ void prologue_kernel(const float* __restrict__ i1w, const float* __restrict__ j1w,
                                const float* __restrict__ i2w, const float* __restrict__ j2w,
                                const int* __restrict__ nn, int B) {
    int idx = blockIdx.x * blockDim.x + threadIdx.x;
    // ---- weight images ----
    if (idx < 16384) {
        const float* w = (idx < 8192) ? i1w : j1w;
        int layer = (idx < 8192) ? 0 : 2;
        int e = idx & 8191;
        int n = e >> 6, k = e & 63;
        float v = w[k * 128 + n];
        if (k < 2) v += w[(64 + k) * 128 + n];
        g_wimg[layer][n * KST1 + k] = __float2half(v);
    } else if (idx < 49152) {
        const float* w = (idx < 32768) ? i2w : j2w;
        int layer = (idx < 32768) ? 1 : 3;
        int e = (idx - 16384) & 16383;
        int n = e >> 7, k = e & 127;
        g_wimg[layer][n * KST2 + k] = __float2half(w[k * 128 + n]);
    }
    // ---- parallel zero of g_pooled ----
    {
        int total4 = (B * RN) >> 2;
        int nthreads = gridDim.x * blockDim.x;
        float4 z = make_float4(0.0f, 0.0f, 0.0f, 0.0f);
        for (int i = idx; i < total4; i += nthreads)
            ((float4*)g_pooled)[i] = z;
    }
    // ---- scan of n_node (block 0 only, 256 threads) ----
    if (blockIdx.x == 0) {
        __shared__ int s[256];
        int tid = threadIdx.x;
        int per = (B + 255) >> 8;
        if (per > 32) per = 32;
        int base = tid * per;
        int loc[32];
        int sum = 0;
        for (int e = 0; e < per; e++) {
            int i2 = base + e;
            int v = (i2 < B) ? nn[i2] : 0;
            loc[e] = v; sum += v;
        }
        s[tid] = sum;
        __syncthreads();
        for (int off = 1; off < 256; off <<= 1) {
            int v = (tid >= off) ? s[tid - off] : 0;
            __syncthreads();
            s[tid] += v;
            __syncthreads();
        }
        int run = s[tid] - sum;
        for (int e = 0; e < per; e++) {
            int i2 = base + e;
            if (i2 < B) { run += loc[e]; g_cumsum[i2] = run; }
        }
    }
}

// ============================ gemm pieces ============================
__device__ __forceinline__ void prefetch_w(uint32_t sb, uint32_t dstOff, int layer, int bytes) {
    const char* src = (const char*)&g_wimg[layer][0];
    uint32_t dst = sb + dstOff;
    int n16 = bytes >> 4;
    for (int i = threadIdx.x; i < n16; i += THREADS)
        cp16(dst + (uint32_t)(i * 16), src + i * 16);
    CP_COMMIT();
}

__device__ __forceinline__ void zero_acc(float acc[2][8][4]) {
#pragma unroll
    for (int a = 0; a < 2; a++)
#pragma unroll
        for (int b = 0; b < 8; b++)
#pragma unroll
            for (int c = 0; c < 4; c++) acc[a][b][c] = 0.0f;
}

// single-pass: A * W; warp covers 32 rows x 64 cols (A fragments issued first)
template <int KSTEPS, int KST>
__device__ __forceinline__ void gemm_pass(uint32_t aBase, uint32_t wBase,
                                          float acc[2][8][4], int wm, int wn, int lane) {
    uint32_t aAddr = aBase + (uint32_t)(((wm * 32 + (lane & 15)) * KST + 8 * (lane >> 4)) * 2);
    uint32_t bAddr = wBase + (uint32_t)(((wn * 64 + (lane & 7) + 8 * (lane >> 4)) * KST
                                         + 8 * ((lane >> 3) & 1)) * 2);
#pragma unroll
    for (int ks = 0; ks < KSTEPS; ks++) {
        uint32_t a0[4], a1[4];
        ldsm4(a0, aAddr); ldsm4(a1, aAddr + 16 * KST * 2); aAddr += 32;
        uint32_t b[4][4];
#pragma unroll
        for (int g = 0; g < 4; g++) ldsm4(b[g], bAddr + g * (16 * KST * 2));
        bAddr += 32;
#pragma unroll
        for (int g = 0; g < 4; g++) {
            mma16816(acc[0][2 * g],     a0, b[g][0], b[g][1]);
            mma16816(acc[0][2 * g + 1], a0, b[g][2], b[g][3]);
            mma16816(acc[1][2 * g],     a1, b[g][0], b[g][1]);
            mma16816(acc[1][2 * g + 1], a1, b[g][2], b[g][3]);
        }
    }
}

// ACT 1 = tanh (HW approx), 2 = selu: bias + act + single-f16 store
template <int ACT>
__device__ __forceinline__ void epilogue_act(float acc[2][8][4], char* sm, int biasIdx,
                                             int wm, int wn, int lane) {
    const float* bias = (const float*)(sm + OFF_BIAS) + biasIdx * 128;
    char* actB = sm + OFF_ACT;
    int mb = wm * 32 + (lane >> 2);
#pragma unroll
    for (int nt = 0; nt < 8; nt++) {
        int n = wn * 64 + nt * 8 + 2 * (lane & 3);
        float2 bv = *(const float2*)&bias[n];
#pragma unroll
        for (int mt = 0; mt < 2; mt++)
#pragma unroll
            for (int half = 0; half < 2; half++) {
                int m = mb + mt * 16 + half * 8;
                float x0 = acc[mt][nt][2 * half]     + bv.x;
                float x1 = acc[mt][nt][2 * half + 1] + bv.y;
                x0 = (ACT == 1) ? fast_tanh(x0) : selu_f(x0);
                x1 = (ACT == 1) ? fast_tanh(x1) : selu_f(x1);
                *(uint32_t*)(actB + (m * KST2 + n) * 2) = pkh2(x0, x1);
            }
    }
}

// ============================ fused main kernel (unchanged from best) ============================
__global__ void __launch_bounds__(THREADS, 2)
fused_kernel(const float* __restrict__ nodes, const float* __restrict__ nmask,
             const float* __restrict__ i1b, const float* __restrict__ i2b,
             const float* __restrict__ j1b, const float* __restrict__ j2b,
             int N, int B) {
    extern __shared__ char sm[];
    uint32_t sb = smem_u32(sm);
    int tid = threadIdx.x;
    int lane = tid & 31, wid = tid >> 5;
    int wm = wid & 3, wn = wid >> 2;     // 4 x 2 warp grid: 32 rows x 64 cols each

    float* biasS = (float*)(sm + OFF_BIAS);
    int*   gidxS = (int*)(sm + OFF_GIDX);
    float* maskS = (float*)(sm + OFF_MASK);

    prefetch_w(sb, OFF_WL1, 0, W1_BYTES);   // Wi1' (group A)
    prefetch_w(sb, OFF_WL2, 1, W2_BYTES);   // Wi2  (group B)

    for (int i = tid; i < 512; i += THREADS) {
        const float* bp = (i < 128) ? i1b : (i < 256) ? i2b : (i < 384) ? j1b : j2b;
        biasS[i] = bp[i & 127];
    }
    if (tid < TILE_M) {
        int gn = blockIdx.x * TILE_M + tid;
        maskS[tid] = (gn < N) ? nmask[gn] : 0.0f;
        int lo = 0, hi = B - 1;
        while (lo < hi) {
            int mid = (lo + hi) >> 1;
            if (gn < g_cumsum[mid]) hi = mid; else lo = mid + 1;
        }
        gidxS[tid] = lo;
    }

    // ---- load + quantize x tile [128 x 64] single f16; 2 threads per row ----
    {
        int m = tid & 127, h = tid >> 7;
        int gn = blockIdx.x * TILE_M + m;
        char* xB = sm + OFF_HX;
        float xv[32];
        if (gn < N) {
#pragma unroll
            for (int v4 = 0; v4 < 8; v4++)
                ((float4*)xv)[v4] = *(const float4*)&nodes[(size_t)gn * 64 + h * 32 + v4 * 4];
        } else {
#pragma unroll
            for (int i = 0; i < 32; i++) xv[i] = 0.0f;
        }
        uint32_t hw[16];
#pragma unroll
        for (int p = 0; p < 16; p++) hw[p] = pkh2(xv[2 * p], xv[2 * p + 1]);
        int base = m * (KST1 * 2) + h * 64;
#pragma unroll
        for (int v4 = 0; v4 < 4; v4++)
            *(uint4*)(xB + base + v4 * 16) = ((uint4*)hw)[v4];
    }

    uint32_t hx = sb + OFF_HX;
    uint32_t ac = sb + OFF_ACT;
    uint32_t wl1 = sb + OFF_WL1, wl2 = sb + OFF_WL2;

    CP_WAIT1();          // Wi1' done
    __syncthreads();

    float acc[2][8][4];
    uint32_t rih[2][8][2];   // i2 output (+bias) packed f16x2

    // ===== G1: i layer-1 (WL1 = Wi1') =====
    zero_acc(acc);
    gemm_pass<KSTEPS1, KST1>(hx, wl1, acc, wm, wn, lane);
    epilogue_act<1>(acc, sm, 0, wm, wn, lane);
    CP_WAIT0();          // Wi2 done
    __syncthreads();

    // ===== G2: i layer-2 (WL2 = Wi2) -> packed regs; copy Wj1' underneath =====
    prefetch_w(sb, OFF_WL1, 2, W1_BYTES);
    zero_acc(acc);
    gemm_pass<KSTEPS2, KST2>(ac, wl2, acc, wm, wn, lane);
    {
        const float* bias = biasS + 1 * 128;
#pragma unroll
        for (int nt = 0; nt < 8; nt++) {
            int n = wn * 64 + nt * 8 + 2 * (lane & 3);
            float2 bv = *(const float2*)&bias[n];
#pragma unroll
            for (int mt = 0; mt < 2; mt++) {
                rih[mt][nt][0] = pkh2(acc[mt][nt][0] + bv.x, acc[mt][nt][1] + bv.y);
                rih[mt][nt][1] = pkh2(acc[mt][nt][2] + bv.x, acc[mt][nt][3] + bv.y);
            }
        }
    }
    CP_WAIT0(); __syncthreads();

    // ===== G3: j layer-1 (WL1 = Wj1'); copy Wj2 underneath =====
    prefetch_w(sb, OFF_WL2, 3, W2_BYTES);
    zero_acc(acc);
    gemm_pass<KSTEPS1, KST1>(hx, wl1, acc, wm, wn, lane);
    epilogue_act<2>(acc, sm, 2, wm, wn, lane);
    CP_WAIT0(); __syncthreads();

    // ===== G4: j layer-2 (WL2 = Wj2) =====
    zero_acc(acc);
    gemm_pass<KSTEPS2, KST2>(ac, wl2, acc, wm, wn, lane);

    // ===== gate + pooled reduction (register path) =====
    {
        const float* bias = biasS + 3 * 128;
        int r0 = wm * 32;
        bool uniform = (gidxS[r0] == gidxS[r0 + 31]);
        int baseRow = r0 + (lane >> 2);
        float mk[2][2];
#pragma unroll
        for (int mt = 0; mt < 2; mt++)
#pragma unroll
            for (int half = 0; half < 2; half++)
                mk[mt][half] = maskS[baseRow + mt * 16 + half * 8];

        if (uniform) {
            int g = gidxS[r0];
#pragma unroll
            for (int nt = 0; nt < 8; nt++) {
                int n = wn * 64 + nt * 8 + 2 * (lane & 3);
                float2 bv = *(const float2*)&bias[n];
                float sg[2][2][2];
#pragma unroll
                for (int mt = 0; mt < 2; mt++)
#pragma unroll
                    for (int half = 0; half < 2; half++) {
                        float2 iv = uph2(rih[mt][nt][half]);
                        sg[mt][half][0] = sigmoid_fast(iv.x) * mk[mt][half];
                        sg[mt][half][1] = sigmoid_fast(iv.y) * mk[mt][half];
                    }
                float s0 = 0.0f, s1 = 0.0f;
#pragma unroll
                for (int mt = 0; mt < 2; mt++)
#pragma unroll
                    for (int half = 0; half < 2; half++) {
                        s0 = fmaf(sg[mt][half][0], acc[mt][nt][2 * half] + bv.x, s0);
                        s1 = fmaf(sg[mt][half][1], acc[mt][nt][2 * half + 1] + bv.y, s1);
                    }
#pragma unroll
                for (int st = 4; st <= 16; st <<= 1) {
                    s0 += __shfl_xor_sync(0xffffffffu, s0, st);
                    s1 += __shfl_xor_sync(0xffffffffu, s1, st);
                }
                if ((lane >> 2) == 0) {
                    int nc = wn * 64 + nt * 8 + 2 * lane;
                    atomicAdd(&g_pooled[g * RN + nc], s0);
                    atomicAdd(&g_pooled[g * RN + nc + 1], s1);
                }
            }
        } else {
#pragma unroll
            for (int nt = 0; nt < 8; nt++) {
                int n = wn * 64 + nt * 8 + 2 * (lane & 3);
                float2 bv = *(const float2*)&bias[n];
#pragma unroll
                for (int mt = 0; mt < 2; mt++)
#pragma unroll
                    for (int half = 0; half < 2; half++) {
                        int r = baseRow + mt * 16 + half * 8;
                        int g = gidxS[r];
                        float2 iv = uph2(rih[mt][nt][half]);
                        float v0 = sigmoid_fast(iv.x)
                                   * (acc[mt][nt][2 * half] + bv.x) * mk[mt][half];
                        float v1 = sigmoid_fast(iv.y)
                                   * (acc[mt][nt][2 * half + 1] + bv.y) * mk[mt][half];
                        atomicAdd(&g_pooled[g * RN + n], v0);
                        atomicAdd(&g_pooled[g * RN + n + 1], v1);
                    }
            }
        }
    }
}

// ============================ final per-graph MLP (split-K8, 8 warps/graph) ============================
__global__ void final_kernel(const float* __restrict__ h1w, const float* __restrict__ h1b,
                             const float* __restrict__ h2w, const float* __restrict__ h2b,
                             float* __restrict__ out, int B) {
    __shared__ float ps[RN];             // pooled row
    __shared__ float pstage[7][132];     // partials from k-eighths 1..7
    int g = blockIdx.x;
    if (g >= B) return;
    int tid = threadIdx.x;
    if (tid < 32) {
        *(float4*)&ps[tid * 4] = *(const float4*)&g_pooled[(size_t)g * RN + tid * 4];
    }
    __syncthreads();

    int w = tid >> 5, lane = tid & 31;   // w = k-eighth
    float a0, a1, a2, a3;
    if (w == 0) {
        float4 bv = ((const float4*)h1b)[lane];
        a0 = bv.x; a1 = bv.y; a2 = bv.z; a3 = bv.w;
    } else {
        a0 = a1 = a2 = a3 = 0.0f;
    }
    const float* pr = &ps[w * 16];
    const float* wb = h1w + (size_t)w * 16 * RN;
#pragma unroll
    for (int k = 0; k < 16; k++) {
        float pv = pr[k];
        float4 wv = *(const float4*)(wb + k * RN + (lane << 2));
        a0 = fmaf(pv, wv.x, a0);
        a1 = fmaf(pv, wv.y, a1);
        a2 = fmaf(pv, wv.z, a2);
        a3 = fmaf(pv, wv.w, a3);
    }
    if (w != 0) {
        pstage[w - 1][lane * 4 + 0] = a0;
        pstage[w - 1][lane * 4 + 1] = a1;
        pstage[w - 1][lane * 4 + 2] = a2;
        pstage[w - 1][lane * 4 + 3] = a3;
    }
    __syncthreads();
    if (w == 0) {
#pragma unroll
        for (int q = 0; q < 7; q++) {
            a0 += pstage[q][lane * 4 + 0];
            a1 += pstage[q][lane * 4 + 1];
            a2 += pstage[q][lane * 4 + 2];
            a3 += pstage[q][lane * 4 + 3];
        }
        a0 = selu_f(a0); a1 = selu_f(a1); a2 = selu_f(a2); a3 = selu_f(a3);
        float4 h2 = ((const float4*)h2w)[lane];
        float part = a0 * h2.x + a1 * h2.y + a2 * h2.z + a3 * h2.w;
#pragma unroll
        for (int off = 16; off > 0; off >>= 1)
            part += __shfl_down_sync(0xffffffffu, part, off);
        if (lane == 0) out[g] = part + h2b[0];
    }
}

// ============================ launch ============================
extern "C" void kernel_launch(void* const* d_in, const int* in_sizes, int n_in,
                              void* d_out, int out_size) {
    const float* nodes = (const float*)d_in[0];
    const float* nmask = (const float*)d_in[1];
    const int*   n_node = (const int*)d_in[2];
    const float* i1w = (const float*)d_in[3];
    const float* i1b = (const float*)d_in[4];
    const float* i2w = (const float*)d_in[5];
    const float* i2b = (const float*)d_in[6];
    const float* j1w = (const float*)d_in[7];
    const float* j1b = (const float*)d_in[8];
    const float* j2w = (const float*)d_in[9];
    const float* j2b = (const float*)d_in[10];
    const float* h1w = (const float*)d_in[11];
    const float* h1b = (const float*)d_in[12];
    const float* h2w = (const float*)d_in[13];
    const float* h2b = (const float*)d_in[14];

    int N = in_sizes[1];
    int B = in_sizes[2];

    prologue_kernel<<<192, 256>>>(i1w, j1w, i2w, j2w, n_node, B);

    cudaFuncSetAttribute(fused_kernel, cudaFuncAttributeMaxDynamicSharedMemorySize, SMEM_SZ);
    int grid = (N + TILE_M - 1) / TILE_M;
    fused_kernel<<<grid, THREADS, SMEM_SZ>>>(nodes, nmask, i1b, i2b, j1b, j2b, N, B);

    final_kernel<<<B, 256>>>(h1w, h1b, h2w, h2b, (float*)d_out, B);
}